// round 15
// baseline (speedup 1.0000x reference)
#include <cuda_runtime.h>
#include <math.h>
#include <stdint.h>

#define NT      128            // 4 warps/block, 1 batch element per thread
#define NB      512            // 65536 / NT
#define TSTEPS  128
#define TT      8              // timesteps per tile
#define NTILES  16             // TSTEPS / TT
#define NSTAGE  3              // per-warp cp.async ring depth
#define ROW4    7              // float4s per smem row (6 data + 1 pad) -> conflict-free LDS.128
#define WROWS   32             // rows (elements) per warp
#define WTILE4  (WROWS * ROW4) // 224 float4 per warp-stage
#define WBUF4   (NSTAGE * WTILE4)
#define NPAIRS  (TSTEPS / 2)   // 64 time-pairs

typedef unsigned long long u64;

static __device__ float g_partial[NB];
static __device__ unsigned int g_count = 0;

__device__ __forceinline__ float tanha(float x) {
    float y; asm("tanh.approx.f32 %0, %1;" : "=f"(y) : "f"(x)); return y;
}
__device__ __forceinline__ u64 pk(float lo, float hi) {
    u64 d; asm("mov.b64 %0, {%1, %2};" : "=l"(d) : "f"(lo), "f"(hi)); return d;
}
__device__ __forceinline__ void upk(float& lo, float& hi, u64 v) {
    asm("mov.b64 {%0, %1}, %2;" : "=f"(lo), "=f"(hi) : "l"(v));
}
__device__ __forceinline__ u64 fma2(u64 a, u64 b, u64 c) {
    u64 d; asm("fma.rn.f32x2 %0, %1, %2, %3;" : "=l"(d) : "l"(a), "l"(b), "l"(c)); return d;
}
__device__ __forceinline__ void cp_async16(uint32_t dst, const float4* src) {
    asm volatile("cp.async.cg.shared.global [%0], [%1], 16;" :: "r"(dst), "l"(src));
}

__global__ __launch_bounds__(NT, 4)   // pin regs <= 128, keep 4 blocks/SM residency
void recdyn_kernel(const float* __restrict__ hist,   // (B,1,T,3)
                   const float* __restrict__ h0,
                   const float* __restrict__ c0,
                   const float* __restrict__ target,
                   const float* __restrict__ Wih,    // (4,3)
                   const float* __restrict__ Whh,    // (4,1)
                   const float* __restrict__ bih,
                   const float* __restrict__ bhh,
                   const float* __restrict__ Wm,     // (3,128)
                   const float* __restrict__ bm,
                   const float* __restrict__ Wv,     // (6,128)
                   const float* __restrict__ bv,
                   float* __restrict__ out)
{
    // head weights, PRE-HALVED (absorb h2=2h), time-pair interleaved:
    // pair p, entry j (0..8): (w_j[2p], w_j[2p+1]); entry 9 = pad
    __shared__ __align__(16) u64 sw2[NPAIRS * 10];
    __shared__ float sred[NT];
    __shared__ __align__(16) float sbuf[4 * WBUF4 * 4];   // 4 warps x 3-stage rings
    __shared__ int slast;

    const int tid  = threadIdx.x;
    const int lane = tid & 31;
    const int wid  = tid >> 5;
    const int b    = blockIdx.x * NT + tid;

    for (int i = tid; i < NPAIRS * 9; i += NT) {
        int p = i / 9, j = i % 9;
        int t0 = 2 * p;
        float w0, w1;
        if (j < 3) { w0 = Wm[j * TSTEPS + t0]; w1 = Wm[j * TSTEPS + t0 + 1]; }
        else       { w0 = Wv[(j - 3) * TSTEPS + t0]; w1 = Wv[(j - 3) * TSTEPS + t0 + 1]; }
        reinterpret_cast<float2*>(sw2)[p * 10 + j] = make_float2(0.5f * w0, 0.5f * w1);
    }
    __syncthreads();   // sw2 ready; no block-wide barriers until the reduction

    // ---- per-warp staging: 192 f4 slots/tile, 6 per lane ----
    const int seg0 = lane / 6;
    const int q0   = lane - seg0 * 6;
    const float4* gwarp = reinterpret_cast<const float4*>(hist)
                        + ((size_t)blockIdx.x * NT + wid * WROWS) * 96;
    float* wbase = sbuf + (size_t)wid * WBUF4 * 4;
    const uint32_t wbase_u32 = (uint32_t)__cvta_generic_to_shared(wbase);

    #pragma unroll
    for (int pg = 0; pg < 2; ++pg) {
        const float4* src = gwarp + pg * 6;
        uint32_t dstb = wbase_u32 + (uint32_t)(pg * WTILE4) * 16u;
        int s = seg0, qq = q0;
        #pragma unroll
        for (int k = 0; k < 6; ++k) {
            cp_async16(dstb + (uint32_t)(s * ROW4 + qq) * 16u,
                       src + (size_t)s * 96 + qq);
            s += 5; qq += 2; if (qq >= 6) { qq -= 6; ++s; }
        }
        asm volatile("cp.async.commit_group;");
    }

    // ---- rotation matrix from last 3 timesteps ----
    const float4* xr = reinterpret_cast<const float4*>(hist + (size_t)b * (TSTEPS * 3));
    float4 r93 = xr[93];
    float4 r94 = xr[94];
    float4 r95 = xr[95];

    float v1x = r95.y, v1y = r95.z, v1z = r95.w;   // t = 127
    float v2x = r94.z, v2y = r94.w, v2z = r95.x;   // t = 126
    float v3x = r93.w, v3y = r94.x, v3z = r94.y;   // t = 125

    float n1 = rsqrtf(v1x*v1x + v1y*v1y + v1z*v1z);
    float b1x = v1x*n1, b1y = v1y*n1, b1z = v1z*n1;

    float p  = v2x*b1x + v2y*b1y + v2z*b1z;
    float a2x = v2x - p*b1x, a2y = v2y - p*b1y, a2z = v2z - p*b1z;
    float n2 = rsqrtf(a2x*a2x + a2y*a2y + a2z*a2z);
    float b2x = a2x*n2, b2y = a2y*n2, b2z = a2z*n2;

    float b3x = b1y*b2z - b1z*b2y;
    float b3y = b1z*b2x - b1x*b2z;
    float b3z = b1x*b2y - b1y*b2x;

    float sgn = (v3x*b3x + v3y*b3y + v3z*b3z) > 0.0f ? 1.0f : -1.0f;
    float c3x = sgn*b3x, c3y = sgn*b3y, c3z = sgn*b3z;

    // ---- rotate target EARLY so the 9 basis registers can die ----
    float tx = target[b*3+0], ty = target[b*3+1], tz = target[b*3+2];
    const float rt0 = tx*b1x + ty*b1y + tz*b1z;
    const float rt1 = tx*b2x + ty*b2y + tz*b2z;
    const float rt2 = tx*c3x + ty*c3y + tz*c3z;

    // ---- fold rotation into input weights; i,f,o rows pre-scaled by 0.5;
    //      DUPLICATED into f32x2 pairs for time-paired xp ----
    float wihr[12];
    #pragma unroll
    for (int k = 0; k < 12; ++k) wihr[k] = Wih[k];

    u64 wpD[4][3], bbD[4];
    float wh[4];
    #pragma unroll
    for (int k = 0; k < 4; ++k) {
        float s = (k == 2) ? 1.0f : 0.5f;
        float w0 = s * (wihr[k*3+0]*b1x + wihr[k*3+1]*b2x + wihr[k*3+2]*c3x);
        float w1 = s * (wihr[k*3+0]*b1y + wihr[k*3+1]*b2y + wihr[k*3+2]*c3y);
        float w2 = s * (wihr[k*3+0]*b1z + wihr[k*3+1]*b2z + wihr[k*3+2]*c3z);
        wpD[k][0] = pk(w0, w0);
        wpD[k][1] = pk(w1, w1);
        wpD[k][2] = pk(w2, w2);
        float bbv = s * (bih[k] + bhh[k]);
        bbD[k] = pk(bbv, bbv);
        wh[k]  = 0.5f * s * Whh[k];       // extra 0.5 absorbs h2 = 2h
    }

    float h2 = 2.0f * h0[b];              // carry 2h
    float c  = c0[b];
    // time-paired head accumulators: acc[j] = (sum_even h*w_j, sum_odd h*w_j)
    u64 acc[9];
    #pragma unroll
    for (int j = 0; j < 9; ++j) acc[j] = pk(0.f, 0.f);

    for (int g = 0; g < NTILES; ++g) {
        if (g + 2 < NTILES) {
            const float4* src = gwarp + (g + 2) * 6;
            uint32_t dstb = wbase_u32 + (uint32_t)(((g + 2) % NSTAGE) * WTILE4) * 16u;
            int s = seg0, qq = q0;
            #pragma unroll
            for (int k = 0; k < 6; ++k) {
                cp_async16(dstb + (uint32_t)(s * ROW4 + qq) * 16u,
                           src + (size_t)s * 96 + qq);
                s += 5; qq += 2; if (qq >= 6) { qq -= 6; ++s; }
            }
            asm volatile("cp.async.commit_group;");
            asm volatile("cp.async.wait_group 2;");
        } else if (g + 1 < NTILES) {
            asm volatile("cp.async.wait_group 1;");
        } else {
            asm volatile("cp.async.wait_group 0;");
        }
        __syncwarp();

        const float4* brow = reinterpret_cast<const float4*>(wbase)
                           + (g % NSTAGE) * WTILE4 + lane * ROW4;

        #pragma unroll
        for (int half = 0; half < 2; ++half) {
            float4 p0 = brow[half*3 + 0];
            float4 p1 = brow[half*3 + 1];
            float4 p2 = brow[half*3 + 2];
            float xs[12] = {p0.x,p0.y,p0.z,p0.w, p1.x,p1.y,p1.z,p1.w, p2.x,p2.y,p2.z,p2.w};

            #pragma unroll
            for (int pp = 0; pp < 2; ++pp) {
                // ---- time-paired x projection: lanes = (step A, step B) ----
                u64 X0 = pk(xs[6*pp+0], xs[6*pp+3]);
                u64 X1 = pk(xs[6*pp+1], xs[6*pp+4]);
                u64 X2 = pk(xs[6*pp+2], xs[6*pp+5]);

                u64 xpP0 = fma2(X0, wpD[0][0], fma2(X1, wpD[0][1], fma2(X2, wpD[0][2], bbD[0])));
                u64 xpP1 = fma2(X0, wpD[1][0], fma2(X1, wpD[1][1], fma2(X2, wpD[1][2], bbD[1])));
                u64 xpP2 = fma2(X0, wpD[2][0], fma2(X1, wpD[2][1], fma2(X2, wpD[2][2], bbD[2])));
                u64 xpP3 = fma2(X0, wpD[3][0], fma2(X1, wpD[3][1], fma2(X2, wpD[3][2], bbD[3])));

                float xpA0, xpB0, xpA1, xpB1, xpA2, xpB2, xpA3, xpB3;
                upk(xpA0, xpB0, xpP0);
                upk(xpA1, xpB1, xpP1);
                upk(xpA2, xpB2, xpP2);
                upk(xpA3, xpB3, xpP3);

                float h2a, h2b;

                // ---- step A ----
                {
                    float gi = fmaf(h2, wh[0], xpA0);
                    float gf = fmaf(h2, wh[1], xpA1);
                    float gg = fmaf(h2, wh[2], xpA2);
                    float go = fmaf(h2, wh[3], xpA3);
                    float si = fmaf(tanha(gi), 0.5f, 0.5f);
                    float sf = fmaf(tanha(gf), 0.5f, 0.5f);
                    float tg = tanha(gg);
                    float to_ = tanha(go);
                    c = fmaf(sf, c, si * tg);
                    float tc = tanha(c);
                    h2 = fmaf(to_, tc, tc);
                    h2a = h2;
                }
                // ---- step B ----
                {
                    float gi = fmaf(h2, wh[0], xpB0);
                    float gf = fmaf(h2, wh[1], xpB1);
                    float gg = fmaf(h2, wh[2], xpB2);
                    float go = fmaf(h2, wh[3], xpB3);
                    float si = fmaf(tanha(gi), 0.5f, 0.5f);
                    float sf = fmaf(tanha(gf), 0.5f, 0.5f);
                    float tg = tanha(gg);
                    float to_ = tanha(go);
                    c = fmaf(sf, c, si * tg);
                    float tc = tanha(c);
                    h2 = fmaf(to_, tc, tc);
                    h2b = h2;
                }

                // ---- paired head accumulation (once per 2 steps) ----
                const int pr = (g * 2 + half) * 2 + pp;   // global time-pair index
                u64 Hp = pk(h2a, h2b);
                const ulonglong2* wr = reinterpret_cast<const ulonglong2*>(sw2 + pr * 10);
                ulonglong2 q0v = wr[0];
                ulonglong2 q1v = wr[1];
                ulonglong2 q2v = wr[2];
                ulonglong2 q3v = wr[3];
                u64 w8p = sw2[pr * 10 + 8];

                acc[0] = fma2(Hp, q0v.x, acc[0]);
                acc[1] = fma2(Hp, q0v.y, acc[1]);
                acc[2] = fma2(Hp, q1v.x, acc[2]);
                acc[3] = fma2(Hp, q1v.y, acc[3]);
                acc[4] = fma2(Hp, q2v.x, acc[4]);
                acc[5] = fma2(Hp, q2v.y, acc[5]);
                acc[6] = fma2(Hp, q3v.x, acc[6]);
                acc[7] = fma2(Hp, q3v.y, acc[7]);
                acc[8] = fma2(Hp, w8p,   acc[8]);
            }
        }
        __syncwarp();
    }

    // ---- reduce even/odd lanes, heads + gaussian NLL ----
    float hv[9];
    #pragma unroll
    for (int j = 0; j < 9; ++j) {
        float lo, hi; upk(lo, hi, acc[j]);
        hv[j] = lo + hi;
    }

    float m0 = hv[0] + bm[0], m1 = hv[1] + bm[1], m2 = hv[2] + bm[2];
    float e0 = hv[3] + bv[0], e1 = hv[4] + bv[1], e2 = hv[5] + bv[2];
    float e3 = hv[6] + bv[3], e4 = hv[7] + bv[4], e5 = hv[8] + bv[5];

    float d0 = m0 - rt0, d1 = m1 - rt1, d2 = m2 - rt2;

    float z0 = d0;
    float z1 = d1 - e0 * z0;
    float z2 = d2 - e1 * z0 - e2 * z1;

    float quad = z0*z0*__expf(-e3) + z1*z1*__expf(-e4) + z2*z2*__expf(-e5);
    float val = 0.5f * (__expf(e3) + __expf(e4) + __expf(e5) + quad);

    // ---- block tree reduction (deterministic) ----
    sred[tid] = val;
    __syncthreads();
    #pragma unroll
    for (int off = NT/2; off > 0; off >>= 1) {
        if (tid < off) sred[tid] += sred[tid + off];
        __syncthreads();
    }

    // ---- last-block grid reduction (deterministic fixed order) ----
    if (tid == 0) {
        g_partial[blockIdx.x] = sred[0];
        __threadfence();
        unsigned int n = atomicAdd(&g_count, 1u);
        slast = (n == NB - 1) ? 1 : 0;
    }
    __syncthreads();

    if (slast) {
        float s = 0.0f;
        #pragma unroll
        for (int k = 0; k < NB / NT; ++k)
            s += __ldcg(&g_partial[tid * (NB / NT) + k]);
        sred[tid] = s;
        __syncthreads();
        #pragma unroll
        for (int off = NT/2; off > 0; off >>= 1) {
            if (tid < off) sred[tid] += sred[tid + off];
            __syncthreads();
        }
        if (tid == 0) {
            out[0] = sred[0] * (1.0f / 65536.0f);
            g_count = 0;   // reset for next graph replay
        }
    }
}

extern "C" void kernel_launch(void* const* d_in, const int* in_sizes, int n_in,
                              void* d_out, int out_size)
{
    const float* hist   = (const float*)d_in[0];
    const float* h0     = (const float*)d_in[1];
    const float* c0     = (const float*)d_in[2];
    const float* target = (const float*)d_in[3];
    const float* Wih    = (const float*)d_in[4];
    const float* Whh    = (const float*)d_in[5];
    const float* bih    = (const float*)d_in[6];
    const float* bhh    = (const float*)d_in[7];
    const float* Wm     = (const float*)d_in[8];
    const float* bm     = (const float*)d_in[9];
    const float* Wv     = (const float*)d_in[10];
    const float* bv     = (const float*)d_in[11];

    recdyn_kernel<<<NB, NT>>>(hist, h0, c0, target,
                              Wih, Whh, bih, bhh, Wm, bm, Wv, bv,
                              (float*)d_out);
}

// round 16
// speedup vs baseline: 1.0779x; 1.0779x over previous
#include <cuda_runtime.h>
#include <math.h>
#include <stdint.h>

#define NT      128            // 4 warps/block, 1 batch element per thread
#define NB      512            // 65536 / NT
#define TSTEPS  128
#define TT      8              // timesteps per tile
#define NTILES  16             // TSTEPS / TT
#define NSTAGE  3              // per-warp cp.async ring depth
#define ROW4    7              // float4s per smem row (6 data + 1 pad) -> conflict-free LDS.128
#define WROWS   32             // rows (elements) per warp
#define WTILE4  (WROWS * ROW4) // 224 float4 per warp-stage
#define WBUF4   (NSTAGE * WTILE4)
#define NPAIRS  (TSTEPS / 2)   // 64 time-pairs

typedef unsigned long long u64;

static __device__ float g_partial[NB];
static __device__ unsigned int g_count = 0;

__device__ __forceinline__ float tanha(float x) {
    float y; asm("tanh.approx.f32 %0, %1;" : "=f"(y) : "f"(x)); return y;
}
__device__ __forceinline__ u64 pk(float lo, float hi) {
    u64 d; asm("mov.b64 %0, {%1, %2};" : "=l"(d) : "f"(lo), "f"(hi)); return d;
}
__device__ __forceinline__ void upk(float& lo, float& hi, u64 v) {
    asm("mov.b64 {%0, %1}, %2;" : "=f"(lo), "=f"(hi) : "l"(v));
}
__device__ __forceinline__ u64 fma2(u64 a, u64 b, u64 c) {
    u64 d; asm("fma.rn.f32x2 %0, %1, %2, %3;" : "=l"(d) : "l"(a), "l"(b), "l"(c)); return d;
}
__device__ __forceinline__ void cp_async16(uint32_t dst, const float4* src) {
    asm volatile("cp.async.cg.shared.global [%0], [%1], 16;" :: "r"(dst), "l"(src));
}

__global__ __launch_bounds__(NT, 4)   // pin regs <= 128, keep 4 blocks/SM residency
void recdyn_kernel(const float* __restrict__ hist,   // (B,1,T,3)
                   const float* __restrict__ h0,
                   const float* __restrict__ c0,
                   const float* __restrict__ target,
                   const float* __restrict__ Wih,    // (4,3)
                   const float* __restrict__ Whh,    // (4,1)
                   const float* __restrict__ bih,
                   const float* __restrict__ bhh,
                   const float* __restrict__ Wm,     // (3,128)
                   const float* __restrict__ bm,
                   const float* __restrict__ Wv,     // (6,128)
                   const float* __restrict__ bv,
                   float* __restrict__ out)
{
    // head weights, PRE-HALVED (absorb h2=2h), time-pair interleaved:
    // sw2:  pair p, entries j=0..7: (w_j[2p], w_j[2p+1])  -> 4x LDS.128 per pair
    // sw8p: pair p: (w_8[2p], w_8[2p+1])                  -> 1x LDS.128 per TWO pairs
    __shared__ __align__(16) u64 sw2[NPAIRS * 8];
    __shared__ __align__(16) u64 sw8p[NPAIRS];
    __shared__ float sred[NT];
    __shared__ __align__(16) float sbuf[4 * WBUF4 * 4];   // 4 warps x 3-stage rings
    __shared__ int slast;

    const int tid  = threadIdx.x;
    const int lane = tid & 31;
    const int wid  = tid >> 5;
    const int b    = blockIdx.x * NT + tid;

    for (int i = tid; i < NPAIRS * 8; i += NT) {
        int p = i >> 3, j = i & 7;
        int t0 = 2 * p;
        float w0, w1;
        if (j < 3) { w0 = Wm[j * TSTEPS + t0]; w1 = Wm[j * TSTEPS + t0 + 1]; }
        else       { w0 = Wv[(j - 3) * TSTEPS + t0]; w1 = Wv[(j - 3) * TSTEPS + t0 + 1]; }
        reinterpret_cast<float2*>(sw2)[i] = make_float2(0.5f * w0, 0.5f * w1);
    }
    for (int p = tid; p < NPAIRS; p += NT) {
        int t0 = 2 * p;
        reinterpret_cast<float2*>(sw8p)[p] =
            make_float2(0.5f * Wv[5 * TSTEPS + t0], 0.5f * Wv[5 * TSTEPS + t0 + 1]);
    }
    __syncthreads();   // weights ready; no block-wide barriers until the reduction

    // ---- per-warp staging: 192 f4 slots/tile, 6 per lane ----
    const int seg0 = lane / 6;
    const int q0   = lane - seg0 * 6;
    const float4* gwarp = reinterpret_cast<const float4*>(hist)
                        + ((size_t)blockIdx.x * NT + wid * WROWS) * 96;
    float* wbase = sbuf + (size_t)wid * WBUF4 * 4;
    const uint32_t wbase_u32 = (uint32_t)__cvta_generic_to_shared(wbase);

    #pragma unroll
    for (int pg = 0; pg < 2; ++pg) {
        const float4* src = gwarp + pg * 6;
        uint32_t dstb = wbase_u32 + (uint32_t)(pg * WTILE4) * 16u;
        int s = seg0, qq = q0;
        #pragma unroll
        for (int k = 0; k < 6; ++k) {
            cp_async16(dstb + (uint32_t)(s * ROW4 + qq) * 16u,
                       src + (size_t)s * 96 + qq);
            s += 5; qq += 2; if (qq >= 6) { qq -= 6; ++s; }
        }
        asm volatile("cp.async.commit_group;");
    }

    // ---- rotation matrix from last 3 timesteps ----
    const float4* xr = reinterpret_cast<const float4*>(hist + (size_t)b * (TSTEPS * 3));
    float4 r93 = xr[93];
    float4 r94 = xr[94];
    float4 r95 = xr[95];

    float v1x = r95.y, v1y = r95.z, v1z = r95.w;   // t = 127
    float v2x = r94.z, v2y = r94.w, v2z = r95.x;   // t = 126
    float v3x = r93.w, v3y = r94.x, v3z = r94.y;   // t = 125

    float n1 = rsqrtf(v1x*v1x + v1y*v1y + v1z*v1z);
    float b1x = v1x*n1, b1y = v1y*n1, b1z = v1z*n1;

    float p  = v2x*b1x + v2y*b1y + v2z*b1z;
    float a2x = v2x - p*b1x, a2y = v2y - p*b1y, a2z = v2z - p*b1z;
    float n2 = rsqrtf(a2x*a2x + a2y*a2y + a2z*a2z);
    float b2x = a2x*n2, b2y = a2y*n2, b2z = a2z*n2;

    float b3x = b1y*b2z - b1z*b2y;
    float b3y = b1z*b2x - b1x*b2z;
    float b3z = b1x*b2y - b1y*b2x;

    float sgn = (v3x*b3x + v3y*b3y + v3z*b3z) > 0.0f ? 1.0f : -1.0f;
    float c3x = sgn*b3x, c3y = sgn*b3y, c3z = sgn*b3z;

    // ---- rotate target EARLY so the 9 basis registers can die ----
    float tx = target[b*3+0], ty = target[b*3+1], tz = target[b*3+2];
    const float rt0 = tx*b1x + ty*b1y + tz*b1z;
    const float rt1 = tx*b2x + ty*b2y + tz*b2z;
    const float rt2 = tx*c3x + ty*c3y + tz*c3z;

    // ---- fold rotation into input weights; i,f,o rows pre-scaled by 0.5 ----
    float wihr[12];
    #pragma unroll
    for (int k = 0; k < 12; ++k) wihr[k] = Wih[k];

    float wp[4][3], wh[4], bbs[4];
    #pragma unroll
    for (int k = 0; k < 4; ++k) {
        float s = (k == 2) ? 1.0f : 0.5f;
        wp[k][0] = s * (wihr[k*3+0]*b1x + wihr[k*3+1]*b2x + wihr[k*3+2]*c3x);
        wp[k][1] = s * (wihr[k*3+0]*b1y + wihr[k*3+1]*b2y + wihr[k*3+2]*c3y);
        wp[k][2] = s * (wihr[k*3+0]*b1z + wihr[k*3+1]*b2z + wihr[k*3+2]*c3z);
        wh[k]  = 0.5f * s * Whh[k];       // extra 0.5 absorbs h2 = 2h
        bbs[k] = s * (bih[k] + bhh[k]);
    }

    float h2 = 2.0f * h0[b];              // carry 2h
    float c  = c0[b];
    // time-paired head accumulators: acc[j] = (sum_even h*w_j, sum_odd h*w_j)
    u64 acc[9];
    #pragma unroll
    for (int j = 0; j < 9; ++j) acc[j] = pk(0.f, 0.f);

    for (int g = 0; g < NTILES; ++g) {
        if (g + 2 < NTILES) {
            const float4* src = gwarp + (g + 2) * 6;
            uint32_t dstb = wbase_u32 + (uint32_t)(((g + 2) % NSTAGE) * WTILE4) * 16u;
            int s = seg0, qq = q0;
            #pragma unroll
            for (int k = 0; k < 6; ++k) {
                cp_async16(dstb + (uint32_t)(s * ROW4 + qq) * 16u,
                           src + (size_t)s * 96 + qq);
                s += 5; qq += 2; if (qq >= 6) { qq -= 6; ++s; }
            }
            asm volatile("cp.async.commit_group;");
            asm volatile("cp.async.wait_group 2;");
        } else if (g + 1 < NTILES) {
            asm volatile("cp.async.wait_group 1;");
        } else {
            asm volatile("cp.async.wait_group 0;");
        }
        __syncwarp();

        const float4* brow = reinterpret_cast<const float4*>(wbase)
                           + (g % NSTAGE) * WTILE4 + lane * ROW4;

        #pragma unroll
        for (int half = 0; half < 2; ++half) {
            float4 p0 = brow[half*3 + 0];
            float4 p1 = brow[half*3 + 1];
            float4 p2 = brow[half*3 + 2];
            float xs[12] = {p0.x,p0.y,p0.z,p0.w, p1.x,p1.y,p1.z,p1.w, p2.x,p2.y,p2.z,p2.w};

            // one LDS.128 covers w8 pairs for BOTH pp iterations of this half
            const int prh = (g * 2 + half) * 2;   // first pair index of this half
            ulonglong2 w8q = *reinterpret_cast<const ulonglong2*>(sw8p + prh);

            #pragma unroll
            for (int pp = 0; pp < 2; ++pp) {
                float h2a, h2b;

                // ---- step A (local step pp*2) ----
                {
                    float x0 = xs[6*pp+0], x1 = xs[6*pp+1], x2 = xs[6*pp+2];
                    float xp0 = fmaf(x0, wp[0][0], fmaf(x1, wp[0][1], fmaf(x2, wp[0][2], bbs[0])));
                    float xp1 = fmaf(x0, wp[1][0], fmaf(x1, wp[1][1], fmaf(x2, wp[1][2], bbs[1])));
                    float xp2 = fmaf(x0, wp[2][0], fmaf(x1, wp[2][1], fmaf(x2, wp[2][2], bbs[2])));
                    float xp3 = fmaf(x0, wp[3][0], fmaf(x1, wp[3][1], fmaf(x2, wp[3][2], bbs[3])));
                    float gi = fmaf(h2, wh[0], xp0);
                    float gf = fmaf(h2, wh[1], xp1);
                    float gg = fmaf(h2, wh[2], xp2);
                    float go = fmaf(h2, wh[3], xp3);
                    float si = fmaf(tanha(gi), 0.5f, 0.5f);
                    float sf = fmaf(tanha(gf), 0.5f, 0.5f);
                    float tg = tanha(gg);
                    float to_ = tanha(go);
                    c = fmaf(sf, c, si * tg);
                    float tc = tanha(c);
                    h2 = fmaf(to_, tc, tc);
                    h2a = h2;
                }
                // ---- step B (local step pp*2+1) ----
                {
                    float x0 = xs[6*pp+3], x1 = xs[6*pp+4], x2 = xs[6*pp+5];
                    float xp0 = fmaf(x0, wp[0][0], fmaf(x1, wp[0][1], fmaf(x2, wp[0][2], bbs[0])));
                    float xp1 = fmaf(x0, wp[1][0], fmaf(x1, wp[1][1], fmaf(x2, wp[1][2], bbs[1])));
                    float xp2 = fmaf(x0, wp[2][0], fmaf(x1, wp[2][1], fmaf(x2, wp[2][2], bbs[2])));
                    float xp3 = fmaf(x0, wp[3][0], fmaf(x1, wp[3][1], fmaf(x2, wp[3][2], bbs[3])));
                    float gi = fmaf(h2, wh[0], xp0);
                    float gf = fmaf(h2, wh[1], xp1);
                    float gg = fmaf(h2, wh[2], xp2);
                    float go = fmaf(h2, wh[3], xp3);
                    float si = fmaf(tanha(gi), 0.5f, 0.5f);
                    float sf = fmaf(tanha(gf), 0.5f, 0.5f);
                    float tg = tanha(gg);
                    float to_ = tanha(go);
                    c = fmaf(sf, c, si * tg);
                    float tc = tanha(c);
                    h2 = fmaf(to_, tc, tc);
                    h2b = h2;
                }

                // ---- paired head accumulation (once per 2 steps) ----
                const int pr = prh + pp;   // global time-pair index
                u64 Hp = pk(h2a, h2b);
                const ulonglong2* wr = reinterpret_cast<const ulonglong2*>(sw2 + pr * 8);
                ulonglong2 q0v = wr[0];
                ulonglong2 q1v = wr[1];
                ulonglong2 q2v = wr[2];
                ulonglong2 q3v = wr[3];
                u64 w8pv = pp ? w8q.y : w8q.x;

                acc[0] = fma2(Hp, q0v.x, acc[0]);
                acc[1] = fma2(Hp, q0v.y, acc[1]);
                acc[2] = fma2(Hp, q1v.x, acc[2]);
                acc[3] = fma2(Hp, q1v.y, acc[3]);
                acc[4] = fma2(Hp, q2v.x, acc[4]);
                acc[5] = fma2(Hp, q2v.y, acc[5]);
                acc[6] = fma2(Hp, q3v.x, acc[6]);
                acc[7] = fma2(Hp, q3v.y, acc[7]);
                acc[8] = fma2(Hp, w8pv,  acc[8]);
            }
        }
        __syncwarp();
    }

    // ---- reduce even/odd lanes, heads + gaussian NLL ----
    float hv[9];
    #pragma unroll
    for (int j = 0; j < 9; ++j) {
        float lo, hi; upk(lo, hi, acc[j]);
        hv[j] = lo + hi;
    }

    float m0 = hv[0] + bm[0], m1 = hv[1] + bm[1], m2 = hv[2] + bm[2];
    float e0 = hv[3] + bv[0], e1 = hv[4] + bv[1], e2 = hv[5] + bv[2];
    float e3 = hv[6] + bv[3], e4 = hv[7] + bv[4], e5 = hv[8] + bv[5];

    float d0 = m0 - rt0, d1 = m1 - rt1, d2 = m2 - rt2;

    float z0 = d0;
    float z1 = d1 - e0 * z0;
    float z2 = d2 - e1 * z0 - e2 * z1;

    float quad = z0*z0*__expf(-e3) + z1*z1*__expf(-e4) + z2*z2*__expf(-e5);
    float val = 0.5f * (__expf(e3) + __expf(e4) + __expf(e5) + quad);

    // ---- block tree reduction (deterministic) ----
    sred[tid] = val;
    __syncthreads();
    #pragma unroll
    for (int off = NT/2; off > 0; off >>= 1) {
        if (tid < off) sred[tid] += sred[tid + off];
        __syncthreads();
    }

    // ---- last-block grid reduction (deterministic fixed order) ----
    if (tid == 0) {
        g_partial[blockIdx.x] = sred[0];
        __threadfence();
        unsigned int n = atomicAdd(&g_count, 1u);
        slast = (n == NB - 1) ? 1 : 0;
    }
    __syncthreads();

    if (slast) {
        float s = 0.0f;
        #pragma unroll
        for (int k = 0; k < NB / NT; ++k)
            s += __ldcg(&g_partial[tid * (NB / NT) + k]);
        sred[tid] = s;
        __syncthreads();
        #pragma unroll
        for (int off = NT/2; off > 0; off >>= 1) {
            if (tid < off) sred[tid] += sred[tid + off];
            __syncthreads();
        }
        if (tid == 0) {
            out[0] = sred[0] * (1.0f / 65536.0f);
            g_count = 0;   // reset for next graph replay
        }
    }
}

extern "C" void kernel_launch(void* const* d_in, const int* in_sizes, int n_in,
                              void* d_out, int out_size)
{
    const float* hist   = (const float*)d_in[0];
    const float* h0     = (const float*)d_in[1];
    const float* c0     = (const float*)d_in[2];
    const float* target = (const float*)d_in[3];
    const float* Wih    = (const float*)d_in[4];
    const float* Whh    = (const float*)d_in[5];
    const float* bih    = (const float*)d_in[6];
    const float* bhh    = (const float*)d_in[7];
    const float* Wm     = (const float*)d_in[8];
    const float* bm     = (const float*)d_in[9];
    const float* Wv     = (const float*)d_in[10];
    const float* bv     = (const float*)d_in[11];

    recdyn_kernel<<<NB, NT>>>(hist, h0, c0, target,
                              Wih, Whh, bih, bhh, Wm, bm, Wv, bv,
                              (float*)d_out);
}